// round 1
// baseline (speedup 1.0000x reference)
#include <cuda_runtime.h>
#include <cuda_bf16.h>
#include <cstdint>

// GCN sparse aggregation:
//   out[r, :] += vals[e] * embeds[cols[e], :]  for each edge e with rows[e] == r
// N_NODES = 100000, N_EDGES = 1600000, D = 64, fp32.
//
// Strategy: out is poisoned -> zero it first. Then one RED (returnless atomic)
// pass over edges, 16 lanes per edge, one float4 per lane. All hot data
// (embeds 25.6MB, out 25.6MB, edges 19.2MB) is L2-resident on B300 (~126MB L2).

#define D_FEAT 64
#define LANES_PER_EDGE 16   // D_FEAT/4 float4 components

__global__ void zero_out_kernel(float4* __restrict__ out, int n4) {
    int i = blockIdx.x * blockDim.x + threadIdx.x;
    int stride = gridDim.x * blockDim.x;
    for (; i < n4; i += stride) {
        out[i] = make_float4(0.f, 0.f, 0.f, 0.f);
    }
}

__global__ void __launch_bounds__(256) gcn_scatter_kernel(
    const int*   __restrict__ rows,
    const int*   __restrict__ cols,
    const float* __restrict__ vals,
    const float4* __restrict__ embeds4,   // [N_NODES, 16] float4
    float* __restrict__ out,              // [N_NODES, 64] float
    int n_edges)
{
    int t = blockIdx.x * blockDim.x + threadIdx.x;
    int e    = t >> 4;           // edge index
    int lane = t & 15;           // which float4 of the 64-wide row
    if (e >= n_edges) return;

    int   r = __ldg(&rows[e]);
    int   c = __ldg(&cols[e]);
    float v = __ldg(&vals[e]);

    float4 x = __ldg(&embeds4[(size_t)c * LANES_PER_EDGE + lane]);
    x.x *= v; x.y *= v; x.z *= v; x.w *= v;

    float* dst = out + (size_t)r * D_FEAT + lane * 4;
    // Returnless vector atomic add (sm_90+): 16B per op, no L2 return trip.
    asm volatile(
        "red.global.add.v4.f32 [%0], {%1, %2, %3, %4};"
        :: "l"(dst), "f"(x.x), "f"(x.y), "f"(x.z), "f"(x.w)
        : "memory");
}

extern "C" void kernel_launch(void* const* d_in, const int* in_sizes, int n_in,
                              void* d_out, int out_size)
{
    // metadata order: rows (int32), cols (int32), vals (f32), embeds (f32), n_nodes (int32 scalar)
    const int*   rows   = (const int*)d_in[0];
    const int*   cols   = (const int*)d_in[1];
    const float* vals   = (const float*)d_in[2];
    const float* embeds = (const float*)d_in[3];
    int n_edges = in_sizes[0];

    float* out = (float*)d_out;

    // 1) zero output (poisoned 0xAA before timing)
    int n4 = out_size / 4;
    {
        int threads = 256;
        int blocks = (n4 + threads - 1) / threads;
        if (blocks > 4096) blocks = 4096;
        zero_out_kernel<<<blocks, threads>>>((float4*)out, n4);
    }

    // 2) scatter-add over edges, 16 lanes per edge
    {
        long long total_threads = (long long)n_edges * LANES_PER_EDGE;
        int threads = 256;
        int blocks = (int)((total_threads + threads - 1) / threads);
        gcn_scatter_kernel<<<blocks, threads>>>(
            rows, cols, vals, (const float4*)embeds, out, n_edges);
    }
}